// round 4
// baseline (speedup 1.0000x reference)
#include <cuda_runtime.h>
#include <cstdint>

// Problem constants: N=100000, D=64, H=4, DK=16, E=1600000
#define MAXN 100000
#define MAXE 1600000

// xt = C1*x + C2*(x @ W^T)  where M^4, M=[[1,.25],[-.25,1]] (exact binary fracs)
#define C1 0.62890625f
#define C2 0.9375f
#define ALPHA 0.2f

struct __align__(32) CD { float4 sd; float4 di; };   // sdst + inv-denom, one sector

// Scratch (static device arrays — no allocation allowed)
__device__ float  g_xt[MAXN * 64];    // transformed features (25.6 MB)
__device__ float4 g_ssrc[MAXN];       // per-node per-head src score
__device__ float4 g_sdst[MAXN];       // per-node per-head dst score
__device__ float4 g_denom[MAXN];      // softmax denominators (by col)
__device__ CD     g_cd[MAXN];         // packed {sdst, 1/denom}
__device__ int    g_cnt[MAXN];        // out-degree by row
__device__ int    g_start[MAXN];      // CSR row start
__device__ int    g_cursor[MAXN];     // fill cursor
__device__ int    g_total;            // scan running offset
__device__ int    g_col[MAXE];        // CSR column indices

__device__ __forceinline__ float lrelu(float v) {
    return v > 0.0f ? v : ALPHA * v;
}

// ---------------------------------------------------------------------------
// Zero per-replay state
// ---------------------------------------------------------------------------
__global__ void kZero(int n_nodes) {
    int i = blockIdx.x * blockDim.x + threadIdx.x;
    if (i < n_nodes) {
        g_denom[i] = make_float4(0.f, 0.f, 0.f, 0.f);
        g_cnt[i] = 0;
    }
    if (i == 0) g_total = 0;
}

// ---------------------------------------------------------------------------
// Per-node: xt = C1*x + C2*(x@W^T); per-head scores vs a[:16], a[16:]
// ---------------------------------------------------------------------------
__global__ void __launch_bounds__(256) kNode(
    const float* __restrict__ x, const float* __restrict__ W,
    const float* __restrict__ a, int n_nodes)
{
    __shared__ float4 sW[1024];
    __shared__ float  sA[32];
    for (int k = threadIdx.x; k < 1024; k += blockDim.x)
        sW[k] = ((const float4*)W)[k];
    if (threadIdx.x < 32) sA[threadIdx.x] = a[threadIdx.x];
    __syncthreads();

    int n = blockIdx.x * blockDim.x + threadIdx.x;
    if (n >= n_nodes) return;

    float4 xr[16];
    const float4* xv = (const float4*)(x + (size_t)n * 64);
#pragma unroll
    for (int i = 0; i < 16; i++) xr[i] = xv[i];

    float ss[4] = {0.f, 0.f, 0.f, 0.f};
    float sd[4] = {0.f, 0.f, 0.f, 0.f};
    float4* xtv = (float4*)(g_xt + (size_t)n * 64);

#pragma unroll
    for (int h = 0; h < 4; h++) {
#pragma unroll
        for (int kq = 0; kq < 4; kq++) {
            const int jq = h * 4 + kq;
            float4 xq = xr[jq];
            float4 outq;
#pragma unroll
            for (int m = 0; m < 4; m++) {
                const int j = jq * 4 + m;
                const float4* wr = &sW[j * 16];
                float p = 0.f;
#pragma unroll
                for (int i = 0; i < 16; i++) {
                    float4 w  = wr[i];
                    float4 xx = xr[i];
                    p = fmaf(xx.x, w.x, p);
                    p = fmaf(xx.y, w.y, p);
                    p = fmaf(xx.z, w.z, p);
                    p = fmaf(xx.w, w.w, p);
                }
                float xc = (m == 0) ? xq.x : (m == 1) ? xq.y : (m == 2) ? xq.z : xq.w;
                float t  = fmaf(C2, p, C1 * xc);
                const int k = kq * 4 + m;
                ss[h] = fmaf(t, sA[k],      ss[h]);
                sd[h] = fmaf(t, sA[16 + k], sd[h]);
                if      (m == 0) outq.x = t;
                else if (m == 1) outq.y = t;
                else if (m == 2) outq.z = t;
                else             outq.w = t;
            }
            xtv[jq] = outq;
        }
    }
    g_ssrc[n] = make_float4(ss[0], ss[1], ss[2], ss[3]);
    g_sdst[n] = make_float4(sd[0], sd[1], sd[2], sd[3]);
}

// ---------------------------------------------------------------------------
// Count out-degree per row (reads only row half of edge_index)
// ---------------------------------------------------------------------------
__global__ void __launch_bounds__(256) kCnt(const int* __restrict__ ei, int E) {
    int e = blockIdx.x * blockDim.x + threadIdx.x;
    if (e < E) atomicAdd(&g_cnt[__ldg(ei + e)], 1);
}

// ---------------------------------------------------------------------------
// Exclusive prefix scan of counts (warp-shuffle based, atomic block offset)
// ---------------------------------------------------------------------------
__global__ void __launch_bounds__(1024) kScan(int n_nodes) {
    __shared__ int part[32];
    __shared__ int base;
    int tid = threadIdx.x;
    int lane = tid & 31, wid = tid >> 5;
    int i = blockIdx.x * 1024 + tid;
    int v = (i < n_nodes) ? g_cnt[i] : 0;
    int s = v;
#pragma unroll
    for (int d = 1; d < 32; d <<= 1) {
        int t = __shfl_up_sync(0xffffffffu, s, d);
        if (lane >= d) s += t;
    }
    if (lane == 31) part[wid] = s;
    __syncthreads();
    if (wid == 0) {
        int p = part[lane];
#pragma unroll
        for (int d = 1; d < 32; d <<= 1) {
            int t = __shfl_up_sync(0xffffffffu, p, d);
            if (lane >= d) p += t;
        }
        part[lane] = p;
        if (lane == 31) base = atomicAdd(&g_total, p);
    }
    __syncthreads();
    if (i < n_nodes) {
        int excl = base + s - v + (wid > 0 ? part[wid - 1] : 0);
        g_start[i]  = excl;
        g_cursor[i] = excl;
    }
}

// ---------------------------------------------------------------------------
// Single score pass: accumulate denom[col], drop col index into CSR slot.
// ---------------------------------------------------------------------------
__global__ void __launch_bounds__(256) kFill(const int* __restrict__ ei, int E) {
    int e = blockIdx.x * blockDim.x + threadIdx.x;
    if (e >= E) return;
    int r = __ldg(ei + e);
    int c = __ldg(ei + E + e);
    float4 s1 = g_ssrc[r];
    float4 s2 = g_sdst[c];
    float e0 = __expf(lrelu(s1.x + s2.x));
    float e1 = __expf(lrelu(s1.y + s2.y));
    float e2 = __expf(lrelu(s1.z + s2.z));
    float e3 = __expf(lrelu(s1.w + s2.w));
    float* d = (float*)&g_denom[c];
    asm volatile("red.global.add.v4.f32 [%0], {%1, %2, %3, %4};"
                 :: "l"(d), "f"(e0), "f"(e1), "f"(e2), "f"(e3) : "memory");
    int pos = atomicAdd(&g_cursor[r], 1);
    g_col[pos] = c;
}

// ---------------------------------------------------------------------------
// Pack per-node {sdst, 1/(denom+eps)} into one 32B record
// ---------------------------------------------------------------------------
__global__ void kPack(int n_nodes) {
    int i = blockIdx.x * blockDim.x + threadIdx.x;
    if (i >= n_nodes) return;
    float4 dn = g_denom[i];
    g_cd[i].sd = g_sdst[i];
    g_cd[i].di = make_float4(__frcp_rn(dn.x + 1e-16f), __frcp_rn(dn.y + 1e-16f),
                             __frcp_rn(dn.z + 1e-16f), __frcp_rn(dn.w + 1e-16f));
}

// ---------------------------------------------------------------------------
// Pull: one warp per row. Phase 1: lane j computes w for edge j (expf once per
// edge). Phase 2: shfl-broadcast (c,w); float2-per-lane coalesced gather of
// xt[c]; register accumulation; one clean 256B store per row.
// ---------------------------------------------------------------------------
__global__ void __launch_bounds__(256) kPull(float* __restrict__ out, int n_nodes) {
    int row = blockIdx.x * (blockDim.x >> 5) + (threadIdx.x >> 5);
    if (row >= n_nodes) return;
    int lane = threadIdx.x & 31;
    int start = g_start[row];
    int cnt   = g_cnt[row];
    float4 s1 = g_ssrc[row];   // broadcast load

    const float2* __restrict__ xt2 = (const float2*)g_xt;
    float ax = 0.f, ay = 0.f;

    for (int base = 0; base < cnt; base += 32) {
        int m = min(32, cnt - base);
        int c = 0; float w = 0.f;
        if (lane < m) {
            c = __ldg(&g_col[start + base + lane]);
            float4 sd = __ldg(&g_cd[c].sd);
            float4 di = __ldg(&g_cd[c].di);
            w = 0.25f * (__expf(lrelu(s1.x + sd.x)) * di.x +
                         __expf(lrelu(s1.y + sd.y)) * di.y +
                         __expf(lrelu(s1.z + sd.z)) * di.z +
                         __expf(lrelu(s1.w + sd.w)) * di.w);
        }
        for (int k = 0; k < m; k++) {
            int   ck = __shfl_sync(0xffffffffu, c, k);
            float wk = __shfl_sync(0xffffffffu, w, k);
            float2 xv = __ldg(&xt2[(size_t)ck * 32 + lane]);
            ax = fmaf(wk, xv.x, ax);
            ay = fmaf(wk, xv.y, ay);
        }
    }
    ((float2*)out)[(size_t)row * 32 + lane] = make_float2(ax, ay);
}

// ---------------------------------------------------------------------------
// inputs: x[N*64] f32, edge_index[2*E] i32, edge_weight[E] f32 (unused),
//         W[64*64] f32, a[32] f32   |  output: out[N*64] f32
// ---------------------------------------------------------------------------
extern "C" void kernel_launch(void* const* d_in, const int* in_sizes, int n_in,
                              void* d_out, int out_size) {
    const float* x  = (const float*)d_in[0];
    const int*   ei = (const int*)d_in[1];
    const float* W  = (const float*)d_in[3];
    const float* a  = (const float*)d_in[4];
    float* out = (float*)d_out;

    int N = in_sizes[0] / 64;
    int E = in_sizes[2];

    kZero<<<(N + 255) / 256, 256>>>(N);
    kNode<<<(N + 255) / 256, 256>>>(x, W, a, N);
    kCnt<<<(E + 255) / 256, 256>>>(ei, E);
    kScan<<<(N + 1023) / 1024, 1024>>>(N);
    kFill<<<(E + 255) / 256, 256>>>(ei, E);
    kPack<<<(N + 255) / 256, 256>>>(N);
    kPull<<<(N + 7) / 8, 256>>>(out, N);
}